// round 15
// baseline (speedup 1.0000x reference)
#include <cuda_runtime.h>
#include <math.h>

#define MM      128
#define MP1     129
#define DD      24
#define NN      512
#define LL      256
#define MSTRIDE 132
#define MS2     (2 * MSTRIDE)

#define EMINE   (-(1 << 27))
#define LN2     0.6931471805599453f

// ---------------- device-global scratch (probability domain) ----------------
__device__ __align__(16) float g_cb0[MSTRIDE];
__device__ __align__(16) float g_cb1[MSTRIDE];
__device__ __align__(16) float g_w  [MSTRIDE];
__device__ __align__(16) float g_q00[MSTRIDE];
__device__ __align__(16) float g_q10[MSTRIDE];
__device__ __align__(16) float g_q01[MSTRIDE];
__device__ __align__(16) float g_q11[MSTRIDE];
__device__ __align__(16) float g_c0 [MSTRIDE];
__device__ __align__(16) float g_c1 [MSTRIDE];
__device__ __align__(16) float g_E  [(DD + 1) * MS2];   // interleaved (ea, ei); row DD = 1.0
__device__ __align__(16) int   g_tok[NN * LL];

struct FalseT { static constexpr bool value = false; };
struct TrueT  { static constexpr bool value = true;  };

// ---- extended float primitives ----
__device__ __forceinline__ float escf(float x, int k) {
    k = max(k, -140);
    int b = __float_as_int(x) + (k << 23);
    return __int_as_float(max(b, 0x00800000));
}
__device__ __forceinline__ float sc_of(int k) {
    return __int_as_float(max(127 + k, 0) << 23);
}
__device__ __forceinline__ void enorm1(float& m, int& e) {
    int b = __float_as_int(m);
    int k = (b >> 23) - 127;
    e += k;
    m = __int_as_float(b - (k << 23));
}

// ---- f32x2 packed helpers ----
__device__ __forceinline__ unsigned long long pk2(float a, float b) {
    unsigned long long r;
    asm("mov.b64 %0, {%1, %2};" : "=l"(r) : "f"(a), "f"(b));
    return r;
}
__device__ __forceinline__ void up2(unsigned long long p, float& a, float& b) {
    asm("mov.b64 {%0, %1}, %2;" : "=f"(a), "=f"(b) : "l"(p));
}
__device__ __forceinline__ unsigned long long mul2_(unsigned long long a, unsigned long long b) {
    unsigned long long r;
    asm("mul.rn.f32x2 %0, %1, %2;" : "=l"(r) : "l"(a), "l"(b));
    return r;
}
__device__ __forceinline__ unsigned long long fma2_(unsigned long long a, unsigned long long b,
                                                    unsigned long long c) {
    unsigned long long r;
    asm("fma.rn.f32x2 %0, %1, %2, %3;" : "=l"(r) : "l"(a), "l"(b), "l"(c));
    return r;
}

__device__ __forceinline__ float lse2_acc(float a, float b) {  // prep only
    float mx = fmaxf(a, b);
    float mn = fminf(a, b);
    return mx + log1pf(expf(mn - mx));
}

// ---------------- fused prep ----------------
__global__ void prep(const float* __restrict__ anc,
                     const float* __restrict__ ins,
                     const float* __restrict__ rr,
                     const float* __restrict__ uu,
                     const float* __restrict__ data) {
    int b = blockIdx.x;
    if (b < NN) {
        int t = threadIdx.x;
        const float4* r4 = (const float4*)(data + ((size_t)(b * LL + t)) * DD);
        int tk = DD;
#pragma unroll
        for (int j = 0; j < 6; j++) {
            float4 v = r4[j];
            if (v.x > 0.5f) tk = 4 * j + 0;
            if (v.y > 0.5f) tk = 4 * j + 1;
            if (v.z > 0.5f) tk = 4 * j + 2;
            if (v.w > 0.5f) tk = 4 * j + 3;
        }
        g_tok[b * LL + t] = tk;
        return;
    }

    int m = threadIdx.x;
    if (m < MSTRIDE) {
        g_E[DD * MS2 + 2 * m]     = 1.0f;
        g_E[DD * MS2 + 2 * m + 1] = 1.0f;
    }
    if (m >= MP1) return;

    {
        const float* ar = anc + m * DD;
        const float* ir = ins + m * DD;
        float mxa = -1e30f, mxi = -1e30f;
        for (int d = 0; d < DD; d++) { mxa = fmaxf(mxa, ar[d]); mxi = fmaxf(mxi, ir[d]); }
        float sa = 0.f, si = 0.f;
        for (int d = 0; d < DD; d++) { sa += expf(ar[d] - mxa); si += expf(ir[d] - mxi); }
        float la = mxa + logf(sa), li = mxi + logf(si);
        for (int d = 0; d < DD; d++) {
            g_E[d * MS2 + 2 * m]     = expf(ar[d] - la);
            g_E[d * MS2 + 2 * m + 1] = expf(ir[d] - li);
        }
    }

    float r[3][2], u[3][2];
    for (int c = 0; c < 3; c++) {
        float x0 = rr[(m * 3 + c) * 2 + 0];
        float x1 = rr[(m * 3 + c) * 2 + 1];
        float l2 = lse2_acc(x0, x1);
        r[c][0] = x0 - l2; r[c][1] = x1 - l2;
        x0 = uu[(m * 3 + c) * 2 + 0];
        x1 = uu[(m * 3 + c) * 2 + 1];
        l2 = lse2_acc(x0, x1);
        u[c][0] = x0 - l2; u[c][1] = x1 - l2;
    }
    g_w  [m] = expf(r[2][0] + u[2][1]);
    g_cb0[m] = expf(r[0][0] + u[0][1]);
    g_cb1[m] = expf(r[1][0] + u[1][1]);
    g_q00[m] = expf(r[0][0] + u[0][0]);
    g_q10[m] = expf(r[1][0] + u[1][0]);
    g_q01[m] = expf(r[0][1]);
    g_q11[m] = expf(r[1][1]);
    g_c0 [m] = expf(r[2][0] + u[2][0]);
    g_c1 [m] = expf(r[2][1]);
}

// ------- main: 4 warps/block, TWO sequences per warp (16 lanes each, 8 states/lane) -------
__global__ void __launch_bounds__(128) hmm_fwd(float* __restrict__ out) {
    const unsigned FULL = 0xffffffffu;
    const int wid = threadIdx.x >> 5;
    const int l   = threadIdx.x & 31;
    const int seg = l >> 4;             // 0 = seq A, 1 = seq B
    const int sl  = l & 15;             // lane within segment
    const int m0  = sl * 8;             // 8 states per lane
    const int n   = (blockIdx.x * 4 + wid) * 2 + seg;
    const bool xl = (sl == 15);         // lane holding m=128 extra state

    float cb0[8], cb1[8], wv[8], q00[8], q10[8], q01[8], q11[8];
    unsigned long long cP[8];
#pragma unroll
    for (int q = 0; q < 8; q++) {
        int m = m0 + q;
        cb0[q] = g_cb0[m]; cb1[q] = g_cb1[m]; wv[q] = g_w[m];
        q00[q] = g_q00[m]; q10[q] = g_q10[m];
        q01[q] = g_q01[m]; q11[q] = g_q11[m];
        cP[q]  = pk2(g_c0[m], g_c1[m]);
    }
    const float q00x = xl ? g_q00[MM] : 0.f;
    const float q10x = xl ? g_q10[MM] : 0.f;
    const float q01x = xl ? g_q01[MM] : 0.f;
    const float q11x = xl ? g_q11[MM] : 0.f;
    const float c0x  = xl ? g_c0 [MM] : 0.f;
    const float c1x  = xl ? g_c1 [MM] : 0.f;

    // suffix products for injection: SUF_i = prod wv[i+1..7]
    const float SUF6 = wv[7];
    const float SUF5 = wv[6] * SUF6;
    const float SUF4 = wv[5] * SUF5;
    const float SUF3 = wv[4] * SUF4;
    const float SUF2 = wv[3] * SUF3;
    const float SUF1 = wv[2] * SUF2;
    const float SUF0 = wv[1] * SUF1;
    const float cbW0 = cb0[0] * SUF0;
    const float cbW1 = cb1[0] * SUF0;
    // Bent7 flatten weights: D_i = prod wv[i+1..6], C7 = wv0*D0
    const float D5 = wv[6];
    const float D4 = wv[5] * D5;
    const float D3 = wv[4] * D4;
    const float D2 = wv[3] * D3;
    const float D1 = wv[2] * D2;
    const float D0 = wv[1] * D1;
    const float C7 = wv[0] * D0;

    // segmented prefix of log2(lane aggregate) and scan K constants
    const float Lwl = log2f(((wv[0] * wv[1]) * (wv[2] * wv[3]))
                          * ((wv[4] * wv[5]) * (wv[6] * SUF6)));
    float P = Lwl;
#pragma unroll
    for (int d = 1; d < 16; d <<= 1) {
        float o = __shfl_up_sync(FULL, P, d);
        if (sl >= d) P += o;
    }
    float Km[7]; int Ke[7];
#pragma unroll
    for (int j = 0; j < 7; j++) {
        float Po = __shfl_up_sync(FULL, P, j + 1);
        if (sl >= j + 1) {
            float Kl = P - Po;
            float fe = floorf(Kl);
            Ke[j] = (int)fe;
            Km[j] = exp2f(Kl - fe);
        } else { Km[j] = 0.f; Ke[j] = EMINE; }
    }
    float Km8; int Ke8;
    {
        float Po = __shfl_up_sync(FULL, P, 8);
        if (sl >= 8) {
            float Kl = P - Po;
            float fe = floorf(Kl);
            Ke8 = (int)fe;
            Km8 = exp2f(Kl - fe);
        } else { Km8 = 0.f; Ke8 = EMINE; }
    }

    // state: 8 packed (match, insert) pairs + shared lane exponent
    unsigned long long pm[8];
#pragma unroll
    for (int i = 0; i < 8; i++) pm[i] = 0;
    int ale = EMINE;
    float axm1 = 0.f; int axe = EMINE;
    float axm0 = 0.f; int axe0 = EMINE;
    float srcm = 1.0f; int srce = 0;

    const int* tseq = g_tok + n * LL;

    auto step = [&](int tk, auto LASTC) {
        constexpr bool LAST = decltype(LASTC)::value;

        const float* base = g_E + tk * MS2;
        const ulonglong2 e01 = *(const ulonglong2*)(base + 2 * m0);
        const ulonglong2 e23 = *(const ulonglong2*)(base + 2 * m0 + 4);
        const ulonglong2 e45 = *(const ulonglong2*)(base + 2 * m0 + 8);
        const ulonglong2 e67 = *(const ulonglong2*)(base + 2 * m0 + 12);
        const unsigned long long ExP = *(const unsigned long long*)(base + 2 * MM);
        const unsigned long long Ep[8] = {e01.x, e01.y, e23.x, e23.y,
                                          e45.x, e45.y, e67.x, e67.y};

        float a7m, a7i; up2(pm[7], a7m, a7i); (void)a7i;
        float atopm = __shfl_up_sync(FULL, a7m, 1);
        int   atope = __shfl_up_sync(FULL, ale, 1);
        if (sl == 0) { atopm = srcm; atope = srce; }

        const int e0 = max(atope, ale);
        const float at = atopm * sc_of(atope - e0);
        const float dl = sc_of(ale - e0);
        const unsigned long long dl2 = pk2(dl, dl);
        float x[8], y[8];
#pragma unroll
        for (int i = 0; i < 8; i++) {
            unsigned long long s = mul2_(pm[i], dl2);
            up2(s, x[i], y[i]);
        }

        float b[8], t0v[8], t1v[8];
#pragma unroll
        for (int i = 0; i < 8; i++) {
            float Pv = (i == 0) ? at : x[i - 1];
            b[i]   = Pv * cb0[i] + y[i] * cb1[i];
            t0v[i] = Pv * q00[i] + y[i] * q10[i];
            t1v[i] = Pv * q01[i] + y[i] * q11[i];
        }
        const float u0 = at * cbW0 + y[0] * cbW1;
        const float inj = ((u0 + b[1] * SUF1) + (b[2] * SUF2 + b[3] * SUF3))
                        + ((b[4] * SUF4 + b[5] * SUF5) + (b[6] * SUF6 + b[7]));
        int Bse = e0; float Bsm = inj;

        // round 1: segmented inclusive-of-8 (offsets 1..7)
        {
            float om[7]; int oe[7];
#pragma unroll
            for (int j = 0; j < 7; j++) {
                om[j] = __shfl_up_sync(FULL, Bsm, j + 1) * Km[j];
                oe[j] = __shfl_up_sync(FULL, Bse, j + 1) + Ke[j];
            }
            int Ea = max(Bse, oe[0]), Eb = max(oe[1], oe[2]);
            int Ec = max(oe[3], oe[4]), Ed = max(oe[5], oe[6]);
            int E = max(max(Ea, Eb), max(Ec, Ed));
            float sa = escf(Bsm, Bse - E) + escf(om[0], oe[0] - E);
            float sb = escf(om[1], oe[1] - E) + escf(om[2], oe[2] - E);
            float sc = escf(om[3], oe[3] - E) + escf(om[4], oe[4] - E);
            float sd = escf(om[5], oe[5] - E) + escf(om[6], oe[6] - E);
            Bsm = (sa + sb) + (sc + sd);
            Bse = E;
        }
        // round 2: offset 8 -> inclusive over 16
        {
            float om = __shfl_up_sync(FULL, Bsm, 8) * Km8;
            int   oe = __shfl_up_sync(FULL, Bse, 8) + Ke8;
            int E = max(Bse, oe);
            Bsm = escf(Bsm, Bse - E) + escf(om, oe - E);
            Bse = E;
        }
        float Bexm = __shfl_up_sync(FULL, Bsm, 1);
        int   Bexe = __shfl_up_sync(FULL, Bse, 1);
        if (sl == 0) { Bexm = 0.f; Bexe = EMINE; }

        // single output exponent per lane
        const int Es = max(Bexe, e0);
        const float zsx = escf(Bexm, Bexe - Es);
        const float dsf = sc_of(e0 - Es);
        const unsigned long long ds2 = pk2(dsf, dsf);
        float bs[7];
#pragma unroll
        for (int i = 0; i < 7; i++) bs[i] = b[i] * dsf;

        // element 7 FIRST via flattened Bent7 (releases next-step shfl operands)
        {
            const float B7 = ((zsx * C7 + bs[0] * D0) + (bs[1] * D1 + bs[2] * D2))
                           + ((bs[3] * D3 + bs[4] * D4) + (bs[5] * D5 + bs[6]));
            pm[7] = mul2_(fma2_(pk2(B7, B7), cP[7],
                                mul2_(pk2(t0v[7], t1v[7]), ds2)), Ep[7]);
        }
        // elements 0..6 via recurrent chain (off critical path)
        {
            float Bc = zsx;
#pragma unroll
            for (int i = 0; i < 7; i++) {
                pm[i] = mul2_(fma2_(pk2(Bc, Bc), cP[i],
                                    mul2_(pk2(t0v[i], t1v[i]), ds2)), Ep[i]);
                Bc = Bc * wv[i] + bs[i];
            }
        }
        // m = 128 path (meaningful on sl==15 of each segment)
        {
            const int e2x = max(e0, axe);
            const float psx = x[7] * sc_of(e0 - e2x);
            const float isx = axm1 * sc_of(axe - e2x);
            const float t1x = psx * q01x + isx * q11x;
            const int Exo = max(e2x, Bse);
            const float zsX = escf(Bsm, Bse - Exo);
            const int kk = e2x - Exo;
            float eaxv, eixv; up2(ExP, eaxv, eixv);
            axm1 = (escf(t1x, kk) + zsX * c1x) * eixv;
            if (LAST) {
                const float t0x = psx * q00x + isx * q10x;
                axm0 = (escf(t0x, kk) + zsX * c0x) * eaxv;
                axe0 = Exo;
            }
            axe = Exo;
        }
        ale = Es;
        srcm = 0.f; srce = EMINE;
    };

    auto renorm = [&]() {
        float v0, v1, mxs[8];
#pragma unroll
        for (int i = 0; i < 8; i++) { up2(pm[i], v0, v1); mxs[i] = fmaxf(v0, v1); }
        float mx = fmaxf(fmaxf(fmaxf(mxs[0], mxs[1]), fmaxf(mxs[2], mxs[3])),
                         fmaxf(fmaxf(mxs[4], mxs[5]), fmaxf(mxs[6], mxs[7])));
        int k = (__float_as_int(mx) >> 23) - 127;
        float s = sc_of(-k);
        unsigned long long s2 = pk2(s, s);
#pragma unroll
        for (int i = 0; i < 8; i++) pm[i] = mul2_(pm[i], s2);
        ale += k;
        enorm1(axm1, axe);
    };

    // ---------------- mainloop ----------------
    int tk = tseq[0];
    for (int t = 0; t < 254; t += 2) {
        const int tk1 = tseq[t + 1];
        const int tk2 = tseq[t + 2];
        step(tk, FalseT{});
        step(tk1, FalseT{});
        renorm();
        tk = tk2;
    }
    {
        const int tk255 = tseq[255];
        step(tk, FalseT{});        // t = 254
        step(tk255, TrueT{});      // t = 255 (computes m=128 match state)
    }

    // final logsumexp (segmented over 16 lanes)
    int emax = max(max(axe, axe0), ale);
#pragma unroll
    for (int d = 8; d; d >>= 1) emax = max(emax, __shfl_xor_sync(FULL, emax, d));

    const int kd = ale - emax;
    float s = escf(axm0, axe0 - emax) + escf(axm1, axe - emax);
#pragma unroll
    for (int i = 0; i < 8; i++) {
        float v0, v1; up2(pm[i], v0, v1);
        s += escf(v0, kd) + escf(v1, kd);
    }
#pragma unroll
    for (int d = 8; d; d >>= 1) s += __shfl_xor_sync(FULL, s, d);

    if (sl == 0) out[n] = ((float)emax + log2f(s)) * LN2;
}

// ---------------- entry point ----------------
extern "C" void kernel_launch(void* const* d_in, const int* in_sizes, int n_in,
                              void* d_out, int out_size) {
    const float* anc  = (const float*)d_in[0];  // (129, 24)
    const float* ins  = (const float*)d_in[1];  // (129, 24)
    const float* rr   = (const float*)d_in[2];  // (129, 3, 2)
    const float* uu   = (const float*)d_in[3];  // (129, 3, 2)
    const float* data = (const float*)d_in[4];  // (512, 256, 24)
    (void)in_sizes; (void)n_in; (void)out_size;

    prep<<<NN + 1, LL>>>(anc, ins, rr, uu, data);
    hmm_fwd<<<NN / 8, 128>>>((float*)d_out);   // 64 blocks x 4 warps x 2 seqs/warp
}

// round 16
// speedup vs baseline: 1.3196x; 1.3196x over previous
#include <cuda_runtime.h>
#include <math.h>

#define MM      128
#define MP1     129
#define DD      24
#define NN      512
#define LL      256
#define MSTRIDE 132
#define MS2     (2 * MSTRIDE)

#define EMINE   (-(1 << 27))
#define LN2     0.6931471805599453f

// ---------------- device-global scratch (probability domain) ----------------
__device__ __align__(16) float g_cb0[MSTRIDE];
__device__ __align__(16) float g_cb1[MSTRIDE];
__device__ __align__(16) float g_w  [MSTRIDE];
__device__ __align__(16) float g_q00[MSTRIDE];
__device__ __align__(16) float g_q10[MSTRIDE];
__device__ __align__(16) float g_q01[MSTRIDE];
__device__ __align__(16) float g_q11[MSTRIDE];
__device__ __align__(16) float g_c0 [MSTRIDE];
__device__ __align__(16) float g_c1 [MSTRIDE];
__device__ __align__(16) float g_E  [(DD + 1) * MS2];   // interleaved (ea, ei) pairs; row DD = 1.0
__device__ __align__(16) int   g_tok[NN * LL];

struct FalseT { static constexpr bool value = false; };
struct TrueT  { static constexpr bool value = true;  };

// ---- extended float primitives ----
__device__ __forceinline__ float escf(float x, int k) {
    k = max(k, -140);
    int b = __float_as_int(x) + (k << 23);
    return __int_as_float(max(b, 0x00800000));
}
__device__ __forceinline__ float sc_of(int k) {
    return __int_as_float(max(127 + k, 0) << 23);
}
__device__ __forceinline__ void enorm1(float& m, int& e) {
    int b = __float_as_int(m);
    int k = (b >> 23) - 127;
    e += k;
    m = __int_as_float(b - (k << 23));
}

// ---- f32x2 packed helpers (Blackwell) ----
__device__ __forceinline__ unsigned long long pk2(float a, float b) {
    unsigned long long r;
    asm("mov.b64 %0, {%1, %2};" : "=l"(r) : "f"(a), "f"(b));
    return r;
}
__device__ __forceinline__ void up2(unsigned long long p, float& a, float& b) {
    asm("mov.b64 {%0, %1}, %2;" : "=f"(a), "=f"(b) : "l"(p));
}
__device__ __forceinline__ unsigned long long mul2_(unsigned long long a, unsigned long long b) {
    unsigned long long r;
    asm("mul.rn.f32x2 %0, %1, %2;" : "=l"(r) : "l"(a), "l"(b));
    return r;
}
__device__ __forceinline__ unsigned long long fma2_(unsigned long long a, unsigned long long b,
                                                    unsigned long long c) {
    unsigned long long r;
    asm("fma.rn.f32x2 %0, %1, %2, %3;" : "=l"(r) : "l"(a), "l"(b), "l"(c));
    return r;
}

__device__ __forceinline__ float lse2_acc(float a, float b) {  // prep only
    float mx = fmaxf(a, b);
    float mn = fminf(a, b);
    return mx + log1pf(expf(mn - mx));
}

// ---------------- fused prep (vectorized token extraction) ----------------
__global__ void prep(const float* __restrict__ anc,
                     const float* __restrict__ ins,
                     const float* __restrict__ rr,
                     const float* __restrict__ uu,
                     const float* __restrict__ data) {
    int b = blockIdx.x;
    if (b < NN) {
        int t = threadIdx.x;
        const float4* r4 = (const float4*)(data + ((size_t)(b * LL + t)) * DD);
        int tk = DD;
#pragma unroll
        for (int j = 0; j < 6; j++) {
            float4 v = r4[j];
            if (v.x > 0.5f) tk = 4 * j + 0;
            if (v.y > 0.5f) tk = 4 * j + 1;
            if (v.z > 0.5f) tk = 4 * j + 2;
            if (v.w > 0.5f) tk = 4 * j + 3;
        }
        g_tok[b * LL + t] = tk;
        return;
    }

    int m = threadIdx.x;
    if (m < MSTRIDE) {
        g_E[DD * MS2 + 2 * m]     = 1.0f;
        g_E[DD * MS2 + 2 * m + 1] = 1.0f;
    }
    if (m >= MP1) return;

    // emission softmaxes, interleaved (ea, ei)
    {
        const float* ar = anc + m * DD;
        const float* ir = ins + m * DD;
        float mxa = -1e30f, mxi = -1e30f;
        for (int d = 0; d < DD; d++) { mxa = fmaxf(mxa, ar[d]); mxi = fmaxf(mxi, ir[d]); }
        float sa = 0.f, si = 0.f;
        for (int d = 0; d < DD; d++) { sa += expf(ar[d] - mxa); si += expf(ir[d] - mxi); }
        float la = mxa + logf(sa), li = mxi + logf(si);
        for (int d = 0; d < DD; d++) {
            g_E[d * MS2 + 2 * m]     = expf(ar[d] - la);
            g_E[d * MS2 + 2 * m + 1] = expf(ir[d] - li);
        }
    }

    float r[3][2], u[3][2];
    for (int c = 0; c < 3; c++) {
        float x0 = rr[(m * 3 + c) * 2 + 0];
        float x1 = rr[(m * 3 + c) * 2 + 1];
        float l2 = lse2_acc(x0, x1);
        r[c][0] = x0 - l2; r[c][1] = x1 - l2;
        x0 = uu[(m * 3 + c) * 2 + 0];
        x1 = uu[(m * 3 + c) * 2 + 1];
        l2 = lse2_acc(x0, x1);
        u[c][0] = x0 - l2; u[c][1] = x1 - l2;
    }
    g_w  [m] = expf(r[2][0] + u[2][1]);
    g_cb0[m] = expf(r[0][0] + u[0][1]);
    g_cb1[m] = expf(r[1][0] + u[1][1]);
    g_q00[m] = expf(r[0][0] + u[0][0]);
    g_q10[m] = expf(r[1][0] + u[1][0]);
    g_q01[m] = expf(r[0][1]);
    g_q11[m] = expf(r[1][1]);
    g_c0 [m] = expf(r[2][0] + u[2][0]);
    g_c1 [m] = expf(r[2][1]);
}

// ---------------- main: 4 warps/block (one per SMSP), one sequence per warp ----------------
__global__ void __launch_bounds__(128) hmm_fwd(float* __restrict__ out) {
    const unsigned FULL = 0xffffffffu;
    const int wid = threadIdx.x >> 5;
    const int n = blockIdx.x * 4 + wid;
    const int l = threadIdx.x & 31;
    const int m0 = l * 4;
    const bool lastlane = (l == 31);

    float cb0[4], cb1[4], wv[4], q00[4], q10[4], q01[4], q11[4];
    unsigned long long cP[4];
#pragma unroll
    for (int q = 0; q < 4; q++) {
        int m = m0 + q;
        cb0[q] = g_cb0[m]; cb1[q] = g_cb1[m]; wv[q] = g_w[m];
        q00[q] = g_q00[m]; q10[q] = g_q10[m];
        q01[q] = g_q01[m]; q11[q] = g_q11[m];
        cP[q]  = pk2(g_c0[m], g_c1[m]);
    }
    const float q00x = lastlane ? g_q00[MM] : 0.f;
    const float q10x = lastlane ? g_q10[MM] : 0.f;
    const float q01x = lastlane ? g_q01[MM] : 0.f;
    const float q11x = lastlane ? g_q11[MM] : 0.f;
    const float c0x  = lastlane ? g_c0 [MM] : 0.f;
    const float c1x  = lastlane ? g_c1 [MM] : 0.f;

    const float wv0 = wv[0], wv1 = wv[1], wv2 = wv[2], wv3 = wv[3];
    const float W23  = wv2 * wv3;
    const float W12  = wv1 * wv2;
    const float Wp2  = wv0 * wv1 * wv2;
    const float W123 = wv1 * W23;
    const float cbW0 = cb0[0] * W123;
    const float cbW1 = cb1[0] * W123;

    // lane-aggregate multiplier in log2; warp prefix; K constants as (m, e) pairs
    float Lwl = log2f(wv0 * W123);
    float P = Lwl;
#pragma unroll
    for (int d = 1; d < 32; d <<= 1) {
        float o = __shfl_up_sync(FULL, P, d);
        if (l >= d) P += o;
    }
    float Km[10]; int Ke[10];
    {
        const int offs[10] = {1, 2, 3, 4, 5, 6, 7, 8, 16, 24};
#pragma unroll
        for (int j = 0; j < 10; j++) {
            float Po = __shfl_up_sync(FULL, P, offs[j]);
            if (l >= offs[j]) {
                float Kl = P - Po;
                float fe = floorf(Kl);
                Ke[j] = (int)fe;
                Km[j] = exp2f(Kl - fe);
            } else { Km[j] = 0.f; Ke[j] = EMINE; }
        }
    }

    // state: 4 packed (match, insert) pairs + ONE shared lane exponent
    unsigned long long pm0 = 0, pm1 = 0, pm2 = 0, pm3 = 0;
    int ale = EMINE;
    float axm1 = 0.f; int axe = EMINE;     // insert state m=128
    float axm0 = 0.f; int axe0 = EMINE;    // match state m=128 (final step only)
    float srcm = 1.0f; int srce = 0;

    const int* tn = g_tok + n * LL;

    auto step = [&](unsigned long long Ep0, unsigned long long Ep1,
                    unsigned long long Ep2, unsigned long long Ep3,
                    unsigned long long Epx, auto LASTC) {
        constexpr bool LAST = decltype(LASTC)::value;

        float a03, a13; up2(pm3, a03, a13); (void)a13;
        float atopm = __shfl_up_sync(FULL, a03, 1);
        int   atope = __shfl_up_sync(FULL, ale, 1);
        if (l == 0) { atopm = srcm; atope = srce; }

        // single alignment to e0 = max(atope, ale)
        const int e0 = max(atope, ale);
        const float at = atopm * sc_of(atope - e0);
        const float dl = sc_of(ale - e0);
        const unsigned long long dl2 = pk2(dl, dl);
        const unsigned long long s0p = mul2_(pm0, dl2);
        const unsigned long long s1p = mul2_(pm1, dl2);
        const unsigned long long s2p = mul2_(pm2, dl2);
        const unsigned long long s3p = mul2_(pm3, dl2);
        float x0, y0, x1, y1, x2, y2, x3, y3;
        up2(s0p, x0, y0); up2(s1p, x1, y1); up2(s2p, x2, y2); up2(s3p, x3, y3);

        // plain fp32 in e0 domain
        const float b0 = at * cb0[0] + y0 * cb1[0];
        const float b1 = x0 * cb0[1] + y1 * cb1[1];
        const float b2 = x1 * cb0[2] + y2 * cb1[2];
        const float b3 = x2 * cb0[3] + y3 * cb1[3];
        const float u0 = at * cbW0 + y0 * cbW1;
        const float t00 = at * q00[0] + y0 * q10[0], t10 = at * q01[0] + y0 * q11[0];
        const float t01 = x0 * q00[1] + y1 * q10[1], t11 = x0 * q01[1] + y1 * q11[1];
        const float t02 = x1 * q00[2] + y2 * q10[2], t12 = x1 * q01[2] + y2 * q11[2];
        const float t03 = x2 * q00[3] + y3 * q10[3], t13 = x2 * q01[3] + y3 * q11[3];

        // lane aggregate injection
        int Bse = e0;
        float Bsm = (u0 + b1 * W23) + (b2 * wv3 + b3);

        // warp scan: radix-8 round (1..7), then radix-4 round (8,16,24)
        {
            float om[7]; int oe[7];
#pragma unroll
            for (int j = 0; j < 7; j++) {
                om[j] = __shfl_up_sync(FULL, Bsm, j + 1) * Km[j];
                oe[j] = __shfl_up_sync(FULL, Bse, j + 1) + Ke[j];
            }
            int Ea = max(Bse, oe[0]), Eb = max(oe[1], oe[2]);
            int Ec = max(oe[3], oe[4]), Ed = max(oe[5], oe[6]);
            int E = max(max(Ea, Eb), max(Ec, Ed));
            float sa = escf(Bsm, Bse - E) + escf(om[0], oe[0] - E);
            float sb = escf(om[1], oe[1] - E) + escf(om[2], oe[2] - E);
            float sc = escf(om[3], oe[3] - E) + escf(om[4], oe[4] - E);
            float sd = escf(om[5], oe[5] - E) + escf(om[6], oe[6] - E);
            Bsm = (sa + sb) + (sc + sd);
            Bse = E;

            float p1m = __shfl_up_sync(FULL, Bsm, 8)  * Km[7];
            int   p1e = __shfl_up_sync(FULL, Bse, 8)  + Ke[7];
            float p2m = __shfl_up_sync(FULL, Bsm, 16) * Km[8];
            int   p2e = __shfl_up_sync(FULL, Bse, 16) + Ke[8];
            float p3m = __shfl_up_sync(FULL, Bsm, 24) * Km[9];
            int   p3e = __shfl_up_sync(FULL, Bse, 24) + Ke[9];
            E = max(max(Bse, p1e), max(p2e, p3e));
            Bsm = (escf(Bsm, Bse - E) + escf(p1m, p1e - E))
                + (escf(p2m, p2e - E) + escf(p3m, p3e - E));
            Bse = E;
        }
        float Bexm = __shfl_up_sync(FULL, Bsm, 1);
        int   Bexe = __shfl_up_sync(FULL, Bse, 1);
        if (l == 0) { Bexm = 0.f; Bexe = EMINE; }

        // single output exponent Es (En_i are all equal)
        const int Es = max(Bexe, e0);
        const float zsx = escf(Bexm, Bexe - Es);
        const float dsf = sc_of(e0 - Es);
        const unsigned long long ds2 = pk2(dsf, dsf);
        const float b0s = b0 * dsf, b1s = b1 * dsf, b2s = b2 * dsf;
        const float B1 = zsx * wv0 + b0s;
        const float B2 = B1 * wv1 + b1s;
        const float B3 = (zsx * Wp2 + b0s * W12) + (b1s * wv2 + b2s);

        // outputs (element 3 first to release next-step shfl operands early)
        pm3 = mul2_(fma2_(pk2(B3, B3),   cP[3], mul2_(pk2(t03, t13), ds2)), Ep3);
        pm0 = mul2_(fma2_(pk2(zsx, zsx), cP[0], mul2_(pk2(t00, t10), ds2)), Ep0);
        pm1 = mul2_(fma2_(pk2(B1, B1),   cP[1], mul2_(pk2(t01, t11), ds2)), Ep1);
        pm2 = mul2_(fma2_(pk2(B2, B2),   cP[2], mul2_(pk2(t02, t12), ds2)), Ep2);

        // m = 128 (insert each step; match only on LAST)
        {
            const int e2x = max(e0, axe);
            const float psx = x3 * sc_of(e0 - e2x);
            const float isx = axm1 * sc_of(axe - e2x);
            const float t1x = psx * q01x + isx * q11x;
            const int Ex = max(e2x, Bse);
            const float zsX = escf(Bsm, Bse - Ex);
            const int kk = e2x - Ex;
            float eaxv, eixv; up2(Epx, eaxv, eixv);
            axm1 = (escf(t1x, kk) + zsX * c1x) * eixv;
            if (LAST) {
                const float t0x = psx * q00x + isx * q10x;
                axm0 = (escf(t0x, kk) + zsX * c0x) * eaxv;
                axe0 = Ex;
            }
            axe = Ex;
        }
        ale = Es;
        srcm = 0.f; srce = EMINE;
    };

    auto renorm = [&]() {
        float a0, a1, b0_, b1_, c0_, c1_, d0, d1;
        up2(pm0, a0, a1); up2(pm1, b0_, b1_); up2(pm2, c0_, c1_); up2(pm3, d0, d1);
        float mx = fmaxf(fmaxf(fmaxf(a0, a1), fmaxf(b0_, b1_)),
                         fmaxf(fmaxf(c0_, c1_), fmaxf(d0, d1)));
        int k = (__float_as_int(mx) >> 23) - 127;
        float s = sc_of(-k);
        unsigned long long s2 = pk2(s, s);
        pm0 = mul2_(pm0, s2); pm1 = mul2_(pm1, s2);
        pm2 = mul2_(pm2, s2); pm3 = mul2_(pm3, s2);
        ale += k;
        enorm1(axm1, axe);
    };

    auto ldE = [&](int tk, unsigned long long& A, unsigned long long& B,
                   unsigned long long& C, unsigned long long& D, unsigned long long& X) {
        const float* base = g_E + tk * MS2;
        const ulonglong2 u01 = *(const ulonglong2*)(base + 2 * m0);
        const ulonglong2 u23 = *(const ulonglong2*)(base + 2 * m0 + 4);
        A = u01.x; B = u01.y; C = u23.x; D = u23.y;
        X = *(const unsigned long long*)(base + 2 * MM);
    };

    // ---------------- pipelined mainloop ----------------
    int4 tkc = *(const int4*)(tn);
    unsigned long long E0, E1, E2, E3, EX;
    ldE(tkc.x, E0, E1, E2, E3, EX);

    for (int tt = 0; tt < LL - 4; tt += 4) {
        const int4 tkn = *(const int4*)(tn + tt + 4);
        const int nt[4] = {tkc.y, tkc.z, tkc.w, tkn.x};
#pragma unroll
        for (int k = 0; k < 4; k++) {
            unsigned long long F0, F1, F2, F3, FX;
            ldE(nt[k], F0, F1, F2, F3, FX);
            step(E0, E1, E2, E3, EX, FalseT{});
            E0 = F0; E1 = F1; E2 = F2; E3 = F3; EX = FX;
            if (k & 1) renorm();
        }
        tkc = tkn;
    }
    // final group: steps 252..255 (255 computes m=128 match state)
    {
        const int ct[4] = {tkc.x, tkc.y, tkc.z, tkc.w};
#pragma unroll
        for (int k = 0; k < 3; k++) {
            unsigned long long F0, F1, F2, F3, FX;
            ldE(ct[k + 1], F0, F1, F2, F3, FX);
            step(E0, E1, E2, E3, EX, FalseT{});
            E0 = F0; E1 = F1; E2 = F2; E3 = F3; EX = FX;
            if (k & 1) renorm();
        }
        step(E0, E1, E2, E3, EX, TrueT{});
    }

    // final logsumexp over all states
    int emax = max(axe, axe0);
    emax = max(emax, ale);
#pragma unroll
    for (int d = 16; d; d >>= 1) emax = max(emax, __shfl_xor_sync(FULL, emax, d));

    float a0, a1, b0_, b1_, c0_, c1_, d0, d1;
    up2(pm0, a0, a1); up2(pm1, b0_, b1_); up2(pm2, c0_, c1_); up2(pm3, d0, d1);
    const int kd = ale - emax;
    float s = escf(axm0, axe0 - emax) + escf(axm1, axe - emax);
    s += (escf(a0, kd) + escf(a1, kd)) + (escf(b0_, kd) + escf(b1_, kd));
    s += (escf(c0_, kd) + escf(c1_, kd)) + (escf(d0, kd) + escf(d1, kd));
#pragma unroll
    for (int d = 16; d; d >>= 1) s += __shfl_xor_sync(FULL, s, d);

    if (l == 0) out[n] = ((float)emax + log2f(s)) * LN2;
}

// ---------------- entry point ----------------
extern "C" void kernel_launch(void* const* d_in, const int* in_sizes, int n_in,
                              void* d_out, int out_size) {
    const float* anc  = (const float*)d_in[0];  // (129, 24)
    const float* ins  = (const float*)d_in[1];  // (129, 24)
    const float* rr   = (const float*)d_in[2];  // (129, 3, 2)
    const float* uu   = (const float*)d_in[3];  // (129, 3, 2)
    const float* data = (const float*)d_in[4];  // (512, 256, 24)
    (void)in_sizes; (void)n_in; (void)out_size;

    prep<<<NN + 1, LL>>>(anc, ins, rr, uu, data);
    hmm_fwd<<<NN / 4, 128>>>((float*)d_out);
}